// round 2
// baseline (speedup 1.0000x reference)
#include <cuda_runtime.h>
#include <cuda_bf16.h>

// Shapes
#define B_DIM 2048
#define N_Z 8
#define NOISE 32
#define STATE 1024
#define HID 1024
#define EPI_H 512
#define PRIOR_H 5
#define PRI_N 160   // 32 ensembles * 5

// Scratch (no allocation allowed)
__device__ float g_H[B_DIM * EPI_H];     // xf @ Wep1[0:2048] + bep1 (pre-relu)
__device__ float g_P1[B_DIM * PRI_N];    // relu(x @ Wp1 + bp1)
__device__ float g_W1r[STATE * PRI_N];   // repacked prior weight [k][e*5+h]

// ---------------------------------------------------------------------------
// Repack Wp1[32][1024][5] -> W1r[1024][160]
// ---------------------------------------------------------------------------
__global__ void repack_wp1(const float* __restrict__ Wp1) {
    int idx = blockIdx.x * 256 + threadIdx.x;
    if (idx < STATE * PRI_N) {
        int k = idx / PRI_N;
        int c = idx - k * PRI_N;
        int e = c / PRIOR_H;
        int h = c - e * PRIOR_H;
        g_W1r[idx] = Wp1[e * (STATE * PRIOR_H) + k * PRIOR_H + h];
    }
}

// ---------------------------------------------------------------------------
// GEMM1: g_H[2048][512] = [x|feature] @ Wep1[0:2048] + bep1   (no relu)
// BM=128 BN=64 BK=16, 256 threads, 8x4 register tile, double-buffered smem
// ---------------------------------------------------------------------------
#define E_BM 128
#define E_BN 64
#define E_BK 16
__global__ __launch_bounds__(256) void sgemm_epi(
    const float* __restrict__ X, const float* __restrict__ F,
    const float* __restrict__ W, const float* __restrict__ bias) {
    __shared__ float As[2][E_BK][E_BM + 4];
    __shared__ float Bs[2][E_BK][E_BN];

    const int tid = threadIdx.x;
    const int row0 = blockIdx.y * E_BM;
    const int col0 = blockIdx.x * E_BN;

    const int ar = tid >> 2;          // 0..63
    const int ac4 = tid & 3;          // 0..3  (k group of 4)
    const int bkr = tid >> 4;         // 0..15
    const int bjc = tid & 15;         // 0..15 (j group of 4)
    const int ty = tid >> 4;          // 0..15 -> rows ty*8..+7
    const int tx = tid & 15;          // 0..15 -> cols tx*4..+3

    float acc[8][4];
#pragma unroll
    for (int i = 0; i < 8; i++)
#pragma unroll
        for (int j = 0; j < 4; j++) acc[i][j] = 0.f;

    float4 pa0, pa1, pb;

    // prefetch tile 0
    {
        int k = ac4 * 4;
        const float* src = X;  // k < 1024 for tile 0
        pa0 = *(const float4*)(src + (row0 + ar) * 1024 + k);
        pa1 = *(const float4*)(src + (row0 + ar + 64) * 1024 + k);
        pb  = *(const float4*)(W + bkr * EPI_H + col0 + bjc * 4);
    }
    // store tile 0
    {
        As[0][ac4 * 4 + 0][ar] = pa0.x; As[0][ac4 * 4 + 1][ar] = pa0.y;
        As[0][ac4 * 4 + 2][ar] = pa0.z; As[0][ac4 * 4 + 3][ar] = pa0.w;
        As[0][ac4 * 4 + 0][ar + 64] = pa1.x; As[0][ac4 * 4 + 1][ar + 64] = pa1.y;
        As[0][ac4 * 4 + 2][ar + 64] = pa1.z; As[0][ac4 * 4 + 3][ar + 64] = pa1.w;
        *(float4*)&Bs[0][bkr][bjc * 4] = pb;
    }
    __syncthreads();

    const int NT = 2048 / E_BK;  // 128
    int buf = 0;
    for (int kt = 0; kt < NT; kt++) {
        if (kt + 1 < NT) {
            int kg = (kt + 1) * E_BK + ac4 * 4;
            const float* src = (kg < 1024) ? X : F;
            int kk = kg & 1023;
            pa0 = *(const float4*)(src + (row0 + ar) * 1024 + kk);
            pa1 = *(const float4*)(src + (row0 + ar + 64) * 1024 + kk);
            pb  = *(const float4*)(W + ((kt + 1) * E_BK + bkr) * EPI_H + col0 + bjc * 4);
        }
#pragma unroll
        for (int kk = 0; kk < E_BK; kk++) {
            float4 ra0 = *(const float4*)&As[buf][kk][ty * 8];
            float4 ra1 = *(const float4*)&As[buf][kk][ty * 8 + 4];
            float4 rb  = *(const float4*)&Bs[buf][kk][tx * 4];
            float a[8] = {ra0.x, ra0.y, ra0.z, ra0.w, ra1.x, ra1.y, ra1.z, ra1.w};
            float b[4] = {rb.x, rb.y, rb.z, rb.w};
#pragma unroll
            for (int i = 0; i < 8; i++)
#pragma unroll
                for (int j = 0; j < 4; j++)
                    acc[i][j] = fmaf(a[i], b[j], acc[i][j]);
        }
        if (kt + 1 < NT) {
            int nb = buf ^ 1;
            As[nb][ac4 * 4 + 0][ar] = pa0.x; As[nb][ac4 * 4 + 1][ar] = pa0.y;
            As[nb][ac4 * 4 + 2][ar] = pa0.z; As[nb][ac4 * 4 + 3][ar] = pa0.w;
            As[nb][ac4 * 4 + 0][ar + 64] = pa1.x; As[nb][ac4 * 4 + 1][ar + 64] = pa1.y;
            As[nb][ac4 * 4 + 2][ar + 64] = pa1.z; As[nb][ac4 * 4 + 3][ar + 64] = pa1.w;
            *(float4*)&Bs[nb][bkr][bjc * 4] = pb;
        }
        __syncthreads();
        buf ^= 1;
    }

    float4 bv = *(const float4*)(bias + col0 + tx * 4);
#pragma unroll
    for (int i = 0; i < 8; i++) {
        int r = row0 + ty * 8 + i;
        float4 o;
        o.x = acc[i][0] + bv.x; o.y = acc[i][1] + bv.y;
        o.z = acc[i][2] + bv.z; o.w = acc[i][3] + bv.w;
        *(float4*)(g_H + r * EPI_H + col0 + tx * 4) = o;
    }
}

// ---------------------------------------------------------------------------
// Prior GEMM: g_P1[2048][160] = relu(x @ g_W1r + bp1)
// BM=64 BN=32 BK=16, 128 threads, 4x4 register tile, double-buffered
// ---------------------------------------------------------------------------
#define P_BM 64
#define P_BN 32
#define P_BK 16
__global__ __launch_bounds__(128) void sgemm_prior(
    const float* __restrict__ X, const float* __restrict__ bp1) {
    __shared__ float As[2][P_BK][P_BM + 4];
    __shared__ float Bs[2][P_BK][P_BN];

    const int tid = threadIdx.x;
    const int row0 = blockIdx.y * P_BM;
    const int col0 = blockIdx.x * P_BN;

    const int ar = tid >> 2;      // 0..31
    const int ac4 = tid & 3;
    const int bkr = tid >> 3;     // 0..15
    const int bjc = tid & 7;      // 0..7
    const int ty = tid >> 3;      // 0..15 -> rows ty*4
    const int tx = tid & 7;       // 0..7  -> cols tx*4

    float acc[4][4];
#pragma unroll
    for (int i = 0; i < 4; i++)
#pragma unroll
        for (int j = 0; j < 4; j++) acc[i][j] = 0.f;

    float4 pa0, pa1, pb;
    {
        int k = ac4 * 4;
        pa0 = *(const float4*)(X + (row0 + ar) * STATE + k);
        pa1 = *(const float4*)(X + (row0 + ar + 32) * STATE + k);
        pb  = *(const float4*)(g_W1r + bkr * PRI_N + col0 + bjc * 4);
    }
    {
        As[0][ac4 * 4 + 0][ar] = pa0.x; As[0][ac4 * 4 + 1][ar] = pa0.y;
        As[0][ac4 * 4 + 2][ar] = pa0.z; As[0][ac4 * 4 + 3][ar] = pa0.w;
        As[0][ac4 * 4 + 0][ar + 32] = pa1.x; As[0][ac4 * 4 + 1][ar + 32] = pa1.y;
        As[0][ac4 * 4 + 2][ar + 32] = pa1.z; As[0][ac4 * 4 + 3][ar + 32] = pa1.w;
        *(float4*)&Bs[0][bkr][bjc * 4] = pb;
    }
    __syncthreads();

    const int NT = STATE / P_BK;  // 64
    int buf = 0;
    for (int kt = 0; kt < NT; kt++) {
        if (kt + 1 < NT) {
            int kg = (kt + 1) * P_BK + ac4 * 4;
            pa0 = *(const float4*)(X + (row0 + ar) * STATE + kg);
            pa1 = *(const float4*)(X + (row0 + ar + 32) * STATE + kg);
            pb  = *(const float4*)(g_W1r + ((kt + 1) * P_BK + bkr) * PRI_N + col0 + bjc * 4);
        }
#pragma unroll
        for (int kk = 0; kk < P_BK; kk++) {
            float4 ra = *(const float4*)&As[buf][kk][ty * 4];
            float4 rb = *(const float4*)&Bs[buf][kk][tx * 4];
            float a[4] = {ra.x, ra.y, ra.z, ra.w};
            float b[4] = {rb.x, rb.y, rb.z, rb.w};
#pragma unroll
            for (int i = 0; i < 4; i++)
#pragma unroll
                for (int j = 0; j < 4; j++)
                    acc[i][j] = fmaf(a[i], b[j], acc[i][j]);
        }
        if (kt + 1 < NT) {
            int nb = buf ^ 1;
            As[nb][ac4 * 4 + 0][ar] = pa0.x; As[nb][ac4 * 4 + 1][ar] = pa0.y;
            As[nb][ac4 * 4 + 2][ar] = pa0.z; As[nb][ac4 * 4 + 3][ar] = pa0.w;
            As[nb][ac4 * 4 + 0][ar + 32] = pa1.x; As[nb][ac4 * 4 + 1][ar + 32] = pa1.y;
            As[nb][ac4 * 4 + 2][ar + 32] = pa1.z; As[nb][ac4 * 4 + 3][ar + 32] = pa1.w;
            *(float4*)&Bs[nb][bkr][bjc * 4] = pb;
        }
        __syncthreads();
        buf ^= 1;
    }

    float4 bv = *(const float4*)(bp1 + col0 + tx * 4);
#pragma unroll
    for (int i = 0; i < 4; i++) {
        int r = row0 + ty * 4 + i;
        float4 o;
        o.x = fmaxf(acc[i][0] + bv.x, 0.f);
        o.y = fmaxf(acc[i][1] + bv.y, 0.f);
        o.z = fmaxf(acc[i][2] + bv.z, 0.f);
        o.w = fmaxf(acc[i][3] + bv.w, 0.f);
        *(float4*)(g_P1 + r * PRI_N + col0 + tx * 4) = o;
    }
}

// ---------------------------------------------------------------------------
// Fused epilogue: per (b,n):
//   out = sum_j relu(H[b][j] + z.W1z[:,j]) * (Wep2[j,:].z) + sum_e (p[b,e]+bep2[e]) z[e]
// 512 threads (thread = one j), 8 b per block, weights in registers.
// ---------------------------------------------------------------------------
__global__ __launch_bounds__(512, 1) void epilogue_kernel(
    const float* __restrict__ Z, const float* __restrict__ Wep1,
    const float* __restrict__ Wep2, const float* __restrict__ bep2,
    const float* __restrict__ Wp2, const float* __restrict__ bp2,
    const float* __restrict__ Wp3, const float* __restrict__ bp3,
    float* __restrict__ out) {
    __shared__ __align__(16) float sZ[N_Z * NOISE];  // [n][k]
    __shared__ float sP[NOISE];                      // prior p[e] + bep2[e]
    __shared__ float sRed[16][N_Z];

    const int tid = threadIdx.x;
    const int j = tid;           // 0..511
    const int lane = tid & 31;
    const int warp = tid >> 5;
    const int b0 = blockIdx.x * 8;

    // register-resident weight slices for this j
    float w1z[NOISE];   // Wep1[2048+k][j]
    float w2t[NOISE];   // Wep2[j][k]
#pragma unroll
    for (int k = 0; k < NOISE; k++)
        w1z[k] = Wep1[(2048 + k) * EPI_H + j];
#pragma unroll
    for (int k4 = 0; k4 < NOISE / 4; k4++) {
        float4 v = *(const float4*)(Wep2 + j * NOISE + k4 * 4);
        w2t[k4 * 4 + 0] = v.x; w2t[k4 * 4 + 1] = v.y;
        w2t[k4 * 4 + 2] = v.z; w2t[k4 * 4 + 3] = v.w;
    }

    for (int bi = 0; bi < 8; bi++) {
        const int b = b0 + bi;
        const float Hj = g_H[b * EPI_H + j];

        if (tid >= 256) {
            int t = tid - 256;
            sZ[t] = Z[b * (N_Z * NOISE) + t];
        } else if (tid < 32) {
            // prior MLP for ensemble member e = tid
            int e = tid;
            const float* p1 = g_P1 + b * PRI_N + e * PRIOR_H;
            float h1[PRIOR_H];
#pragma unroll
            for (int h = 0; h < PRIOR_H; h++) h1[h] = p1[h];
            float h2[PRIOR_H];
#pragma unroll
            for (int g = 0; g < PRIOR_H; g++) {
                float s = bp2[e * PRIOR_H + g];
#pragma unroll
                for (int h = 0; h < PRIOR_H; h++)
                    s = fmaf(h1[h], Wp2[e * 25 + h * PRIOR_H + g], s);
                h2[g] = fmaxf(s, 0.f);
            }
            float p = bp3[e];
#pragma unroll
            for (int g = 0; g < PRIOR_H; g++)
                p = fmaf(h2[g], Wp3[e * PRIOR_H + g], p);
            sP[e] = p + bep2[e];
        }
        __syncthreads();

        float part[N_Z];
#pragma unroll
        for (int n = 0; n < N_Z; n++) {
            float hz = 0.f, wz = 0.f;
            const float4* z4 = (const float4*)(sZ + n * NOISE);
#pragma unroll
            for (int k4 = 0; k4 < NOISE / 4; k4++) {
                float4 zv = z4[k4];
                int k = k4 * 4;
                hz = fmaf(zv.x, w1z[k + 0], hz); wz = fmaf(zv.x, w2t[k + 0], wz);
                hz = fmaf(zv.y, w1z[k + 1], hz); wz = fmaf(zv.y, w2t[k + 1], wz);
                hz = fmaf(zv.z, w1z[k + 2], hz); wz = fmaf(zv.z, w2t[k + 2], wz);
                hz = fmaf(zv.w, w1z[k + 3], hz); wz = fmaf(zv.w, w2t[k + 3], wz);
            }
            float h = fmaxf(Hj + hz, 0.f);
            part[n] = h * wz;
        }

        // reduce over 512 threads
#pragma unroll
        for (int n = 0; n < N_Z; n++) {
            float v = part[n];
            v += __shfl_xor_sync(0xffffffffu, v, 16);
            v += __shfl_xor_sync(0xffffffffu, v, 8);
            v += __shfl_xor_sync(0xffffffffu, v, 4);
            v += __shfl_xor_sync(0xffffffffu, v, 2);
            v += __shfl_xor_sync(0xffffffffu, v, 1);
            if (lane == 0) sRed[warp][n] = v;
        }
        __syncthreads();

        if (tid < N_Z) {
            float s = 0.f;
#pragma unroll
            for (int w = 0; w < 16; w++) s += sRed[w][tid];
            const float* zn = sZ + tid * NOISE;
#pragma unroll
            for (int e = 0; e < NOISE; e++) s = fmaf(sP[e], zn[e], s);
            out[b * N_Z + tid] = s;
        }
        __syncthreads();
    }
}

// ---------------------------------------------------------------------------
extern "C" void kernel_launch(void* const* d_in, const int* in_sizes, int n_in,
                              void* d_out, int out_size) {
    const float* x    = (const float*)d_in[0];
    const float* feat = (const float*)d_in[1];
    const float* z    = (const float*)d_in[2];
    const float* Wep1 = (const float*)d_in[3];
    const float* bep1 = (const float*)d_in[4];
    const float* Wep2 = (const float*)d_in[5];
    const float* bep2 = (const float*)d_in[6];
    const float* Wp1  = (const float*)d_in[7];
    const float* bp1  = (const float*)d_in[8];
    const float* Wp2  = (const float*)d_in[9];
    const float* bp2  = (const float*)d_in[10];
    const float* Wp3  = (const float*)d_in[11];
    const float* bp3  = (const float*)d_in[12];
    float* out = (float*)d_out;

    repack_wp1<<<(STATE * PRI_N + 255) / 256, 256>>>(Wp1);
    sgemm_epi<<<dim3(EPI_H / E_BN, B_DIM / E_BM), 256>>>(x, feat, Wep1, bep1);
    sgemm_prior<<<dim3(PRI_N / P_BN, B_DIM / P_BM), 128>>>(x, bp1);
    epilogue_kernel<<<B_DIM / 8, 512>>>(z, Wep1, Wep2, bep2, Wp2, bp2, Wp3, bp3, out);
}